// round 7
// baseline (speedup 1.0000x reference)
#include <cuda_runtime.h>
#include <cuda_bf16.h>
#include <cstdint>

#define MAX_I   100000
#define MAX_B   16384
#define NUM_SEG (MAX_B * 5)
#define CHUNK   16

__device__ float g_rowsum[MAX_I];
__device__ float g_segsum[NUM_SEG];
__device__ float g_segcnt[NUM_SEG];
__device__ float g_dot[MAX_B];
__device__ float g_isum[MAX_B];
__device__ unsigned g_done = 0;

// Bit-exact emulation of the producer reduction for one row (fallback path).
__device__ __forceinline__ float rowsum_exact(const float* __restrict__ Mr, int r) {
    const float4* rp = reinterpret_cast<const float4*>(Mr + (long)r * 64);
    float v[16], t[16];
    #pragma unroll
    for (int p = 0; p < 16; p++) {
        float4 q = rp[p];
        v[p] = (q.x + q.y) + (q.z + q.w);
    }
    #pragma unroll
    for (int o = 8; o; o >>= 1) {
        #pragma unroll
        for (int p = 0; p < 16; p++) t[p] = v[p] + v[p ^ o];
        #pragma unroll
        for (int p = 0; p < 16; p++) v[p] = t[p];
    }
    return v[0];
}

// ---------------------------------------------------------------------------
// Main fused kernel: block classes by blockIdx.x
//   [0, nprod)            : zero accumulators + rowsum (16 rows/warp, MLP=8)
//   [nprod, nprod+ndot)   : per-sample dot/isum precompute (independent)
//   [nprod+ndot, ...+nseg): seg accumulation (preload, wait flag, gather)
// ---------------------------------------------------------------------------
__global__ void __launch_bounds__(256)
mf_main_kernel(const int*   __restrict__ user_idx,
               const int*   __restrict__ item_idx,
               const int*   __restrict__ flat_items,
               const int*   __restrict__ seg_ids,
               const float* __restrict__ user_emb,
               const float* __restrict__ item_emb,
               const float* __restrict__ Mr,
               int Bn, int T, int I,
               int nprod, int ndot) {
    const int b = blockIdx.x;

    if (b < nprod) {
        // ------------------- producer: zero + rowsum -------------------
        const int tidp = b * 256 + threadIdx.x;
        if (tidp < NUM_SEG) {
            g_segsum[tidp] = 0.0f;
            g_segcnt[tidp] = 0.0f;
        }
        const int g    = tidp >> 5;
        const int lane = threadIdx.x & 31;
        const int row0 = g * 16;
        if (row0 < I) {
            const float4* base = reinterpret_cast<const float4*>(Mr) + (long)row0 * 16;
            float s[8];
            if (row0 + 16 <= I) {
                #pragma unroll
                for (int j = 0; j < 8; j++) {
                    float4 v = base[j * 32 + lane];
                    s[j] = (v.x + v.y) + (v.z + v.w);
                }
            } else {
                #pragma unroll
                for (int j = 0; j < 8; j++) {
                    int f = j * 32 + lane;
                    int r = row0 + (f >> 4);
                    if (r < I) {
                        float4 v = base[f];
                        s[j] = (v.x + v.y) + (v.z + v.w);
                    } else s[j] = 0.0f;
                }
            }
            #pragma unroll
            for (int o = 8; o; o >>= 1) {
                #pragma unroll
                for (int j = 0; j < 8; j++)
                    s[j] += __shfl_xor_sync(0xFFFFFFFFu, s[j], o);
            }
            if ((lane & 15) == 0) {
                int rbase = row0 + (lane >> 4);
                #pragma unroll
                for (int j = 0; j < 8; j++) {
                    int r = rbase + j * 2;
                    if (r < I) g_rowsum[r] = s[j];
                }
            }
        }
        __syncthreads();
        __threadfence();
        if (threadIdx.x == 0) atomicAdd(&g_done, 1u);

    } else if (b < nprod + ndot) {
        // ------------------- dot/isum precompute -------------------
        int t2     = (b - nprod) * 256 + threadIdx.x;
        int sample = t2 >> 3;
        int sub    = t2 & 7;
        if (sample >= Bn) return;

        int u = user_idx[sample];
        int i = item_idx[sample];

        const float4* ue = reinterpret_cast<const float4*>(user_emb + (long)u * 64);
        const float4* ie = reinterpret_cast<const float4*>(item_emb + (long)i * 64);

        float4 a0 = ue[sub];
        float4 a1 = ue[sub + 8];
        float4 b0 = ie[sub];
        float4 b1 = ie[sub + 8];

        float dot  = a0.x*b0.x + a0.y*b0.y + a0.z*b0.z + a0.w*b0.w
                   + a1.x*b1.x + a1.y*b1.y + a1.z*b1.z + a1.w*b1.w;
        float isum = b0.x + b0.y + b0.z + b0.w + b1.x + b1.y + b1.z + b1.w;

        #pragma unroll
        for (int o = 4; o; o >>= 1) {
            dot  += __shfl_xor_sync(0xFFFFFFFFu, dot,  o);
            isum += __shfl_xor_sync(0xFFFFFFFFu, isum, o);
        }
        if (sub == 0) {
            g_dot[sample]  = dot;
            g_isum[sample] = isum;
        }

    } else {
        // ------------------- seg accumulation -------------------
        long base = (long)((b - nprod - ndot) * 256 + threadIdx.x) * CHUNK;
        __shared__ int s_ready;

        int4 sg[4], fi[4];
        bool full = (base < T) && (base + CHUNK <= T);
        if (full) {
            const int4* sg4 = reinterpret_cast<const int4*>(seg_ids + base);
            const int4* fi4 = reinterpret_cast<const int4*>(flat_items + base);
            #pragma unroll
            for (int v = 0; v < 4; v++) { sg[v] = sg4[v]; fi[v] = fi4[v]; }
        }

        // wait for producers (bounded spin; fallback is on-demand rowsum)
        if (threadIdx.x == 0) {
            unsigned d = *(volatile unsigned*)&g_done;
            int iters = 0;
            while (d < (unsigned)nprod && iters < 200000) {
                __nanosleep(64);
                d = *(volatile unsigned*)&g_done;
                iters++;
            }
            s_ready = (d >= (unsigned)nprod) ? 1 : 0;
        }
        __syncthreads();
        __threadfence();
        const bool ready = (s_ready != 0);

        if (base >= T) return;

        int   cur   = -1;
        int   tgt   = -1;
        float acc_s = 0.0f;
        float acc_c = 0.0f;

        if (full) {
            #pragma unroll
            for (int v = 0; v < 4; v++) {
                #pragma unroll
                for (int k = 0; k < 4; k++) {
                    int seg = (k == 0) ? sg[v].x : (k == 1) ? sg[v].y : (k == 2) ? sg[v].z : sg[v].w;
                    int it  = (k == 0) ? fi[v].x : (k == 1) ? fi[v].y : (k == 2) ? fi[v].z : fi[v].w;
                    if (seg != cur) {
                        if (cur >= 0) {
                            atomicAdd(&g_segsum[cur], acc_s);
                            atomicAdd(&g_segcnt[cur], acc_c);
                        }
                        cur = seg; acc_s = 0.0f; acc_c = 0.0f;
                        tgt = item_idx[seg / 5];
                    }
                    if (it != tgt) {
                        acc_s += ready ? g_rowsum[it] : rowsum_exact(Mr, it);
                        acc_c += 1.0f;
                    }
                }
            }
        } else {
            int n = (int)((long)T - base);
            for (int t = 0; t < n; t++) {
                int seg = seg_ids[base + t];
                int it  = flat_items[base + t];
                if (seg != cur) {
                    if (cur >= 0) {
                        atomicAdd(&g_segsum[cur], acc_s);
                        atomicAdd(&g_segcnt[cur], acc_c);
                    }
                    cur = seg; acc_s = 0.0f; acc_c = 0.0f;
                    tgt = item_idx[seg / 5];
                }
                if (it != tgt) {
                    acc_s += ready ? g_rowsum[it] : rowsum_exact(Mr, it);
                    acc_c += 1.0f;
                }
            }
        }
        if (cur >= 0) {
            atomicAdd(&g_segsum[cur], acc_s);
            atomicAdd(&g_segcnt[cur], acc_c);
        }
    }
}

// ---------------------------------------------------------------------------
// Combine kernel: one thread per sample; also resets g_done for graph replay.
// ---------------------------------------------------------------------------
__global__ void combine_kernel(const int*   __restrict__ user_idx,
                               const int*   __restrict__ item_idx,
                               const float* __restrict__ user_bias,
                               const float* __restrict__ item_bias,
                               const float* __restrict__ global_avg,
                               float* __restrict__ out,
                               int Bn) {
    if (blockIdx.x == 0 && threadIdx.x == 0) g_done = 0;

    int sample = blockIdx.x * blockDim.x + threadIdx.x;
    if (sample >= Bn) return;

    int u = user_idx[sample];
    int i = item_idx[sample];

    float uu = 0.0f;
    #pragma unroll
    for (int r = 0; r < 5; r++) {
        float c = g_segcnt[sample * 5 + r];
        float s = g_segsum[sample * 5 + r];
        if (c > 0.0f) uu += s * rsqrtf(fmaxf(c, 1.0f));
    }
    float rui = g_dot[sample] + uu * g_isum[sample]
              + user_bias[u] + item_bias[i] + global_avg[0];
    rui = fminf(fmaxf(rui, 1.0f), 5.0f);
    out[sample] = rui;
}

// ---------------------------------------------------------------------------
// Launch
// ---------------------------------------------------------------------------
extern "C" void kernel_launch(void* const* d_in, const int* in_sizes, int n_in,
                              void* d_out, int out_size) {
    const int*   user_idx   = (const int*)  d_in[0];
    const int*   item_idx   = (const int*)  d_in[1];
    const int*   flat_items = (const int*)  d_in[2];
    const int*   seg_ids    = (const int*)  d_in[3];
    const float* user_emb   = (const float*)d_in[4];
    const float* item_emb   = (const float*)d_in[5];
    const float* Mr         = (const float*)d_in[6];
    const float* user_bias  = (const float*)d_in[7];
    const float* item_bias  = (const float*)d_in[8];
    const float* global_avg = (const float*)d_in[9];
    float* out = (float*)d_out;

    const int Bn = in_sizes[0];            // 16384
    const int T  = in_sizes[2];            // 1,638,400
    const int I  = in_sizes[6] / 64;       // 100000

    const int warps  = (I + 15) / 16;                  // 6250
    const int nprod  = (warps + 7) / 8;                // 782 blocks
    const int ndot   = (Bn * 8 + 255) / 256;           // 512 blocks
    const int nchunk = (T + CHUNK - 1) / CHUNK;        // 102400
    const int nseg   = (nchunk + 255) / 256;           // 400 blocks

    mf_main_kernel<<<nprod + ndot + nseg, 256>>>(
        user_idx, item_idx, flat_items, seg_ids,
        user_emb, item_emb, Mr, Bn, T, I, nprod, ndot);

    combine_kernel<<<(Bn + 255) / 256, 256>>>(user_idx, item_idx,
                                              user_bias, item_bias, global_avg,
                                              out, Bn);
}

// round 8
// speedup vs baseline: 1.1825x; 1.1825x over previous
#include <cuda_runtime.h>
#include <cuda_bf16.h>
#include <cstdint>

#define MAX_I   100000
#define MAX_B   16384
#define NUM_SEG (MAX_B * 5)
#define CHUNK   16

__device__ float g_rowsum[MAX_I];
__device__ float g_segsum[NUM_SEG];
__device__ float g_segcnt[NUM_SEG];
__device__ float g_dot[MAX_B];
__device__ float g_isum[MAX_B];

// ---------------------------------------------------------------------------
// Kernel 1: block classes (mutually independent, no intra-kernel sync):
//   [0, nprod): zero accumulators + rowsum (8 rows/warp, MLP=4)  [R3-best]
//   [nprod, nprod+ndot): per-sample dot/isum precompute
// Triggers PDL completion at entry so K2 blocks can dispatch early.
// ---------------------------------------------------------------------------
__global__ void __launch_bounds__(256)
k1_rowsum_dot(const int*   __restrict__ user_idx,
              const int*   __restrict__ item_idx,
              const float* __restrict__ user_emb,
              const float* __restrict__ item_emb,
              const float* __restrict__ Mr,
              int Bn, int I, int nprod) {
#if __CUDA_ARCH__ >= 900
    if (threadIdx.x == 0) cudaTriggerProgrammaticLaunchCompletion();
#endif
    const int b = blockIdx.x;

    if (b < nprod) {
        const int tid  = b * 256 + threadIdx.x;
        if (tid < NUM_SEG) {
            g_segsum[tid] = 0.0f;
            g_segcnt[tid] = 0.0f;
        }
        const int warp = tid >> 5;
        const int lane = threadIdx.x & 31;
        const int row0 = warp * 8;
        if (row0 >= I) return;

        const float4* base = reinterpret_cast<const float4*>(Mr) + (long)row0 * 16;

        float s[4];
        if (row0 + 8 <= I) {
            #pragma unroll
            for (int j = 0; j < 4; j++) {
                float4 v = base[j * 32 + lane];
                s[j] = (v.x + v.y) + (v.z + v.w);
            }
        } else {
            #pragma unroll
            for (int j = 0; j < 4; j++) {
                int f = j * 32 + lane;
                int r = row0 + (f >> 4);
                if (r < I) {
                    float4 v = base[f];
                    s[j] = (v.x + v.y) + (v.z + v.w);
                } else s[j] = 0.0f;
            }
        }
        #pragma unroll
        for (int o = 8; o; o >>= 1) {
            #pragma unroll
            for (int j = 0; j < 4; j++)
                s[j] += __shfl_xor_sync(0xFFFFFFFFu, s[j], o);
        }
        if ((lane & 15) == 0) {
            int rbase = row0 + (lane >> 4);
            #pragma unroll
            for (int j = 0; j < 4; j++) {
                int r = rbase + j * 2;
                if (r < I) g_rowsum[r] = s[j];
            }
        }
    } else {
        // dot/isum precompute: 8 lanes per sample
        int t2     = (b - nprod) * 256 + threadIdx.x;
        int sample = t2 >> 3;
        int sub    = t2 & 7;
        if (sample >= Bn) return;

        int u = user_idx[sample];
        int i = item_idx[sample];

        const float4* ue = reinterpret_cast<const float4*>(user_emb + (long)u * 64);
        const float4* ie = reinterpret_cast<const float4*>(item_emb + (long)i * 64);

        float4 a0 = ue[sub];
        float4 a1 = ue[sub + 8];
        float4 b0 = ie[sub];
        float4 b1 = ie[sub + 8];

        float dot  = a0.x*b0.x + a0.y*b0.y + a0.z*b0.z + a0.w*b0.w
                   + a1.x*b1.x + a1.y*b1.y + a1.z*b1.z + a1.w*b1.w;
        float isum = b0.x + b0.y + b0.z + b0.w + b1.x + b1.y + b1.z + b1.w;

        #pragma unroll
        for (int o = 4; o; o >>= 1) {
            dot  += __shfl_xor_sync(0xFFFFFFFFu, dot,  o);
            isum += __shfl_xor_sync(0xFFFFFFFFu, isum, o);
        }
        if (sub == 0) {
            g_dot[sample]  = dot;
            g_isum[sample] = isum;
        }
    }
}

// ---------------------------------------------------------------------------
// Kernel 2: segmented accumulation (PDL: preload inputs, then grid-dep sync
// before touching g_rowsum / g_segsum). Triggers for K3 at entry.
// ---------------------------------------------------------------------------
__global__ void __launch_bounds__(256)
k2_seg_accum(const int* __restrict__ flat_items,
             const int* __restrict__ seg_ids,
             const int* __restrict__ item_idx,
             int T) {
#if __CUDA_ARCH__ >= 900
    if (threadIdx.x == 0) cudaTriggerProgrammaticLaunchCompletion();
#endif
    long base = (long)(blockIdx.x * blockDim.x + threadIdx.x) * CHUNK;

    int4 sg[4], fi[4];
    const bool inb  = (base < T);
    const bool full = inb && (base + CHUNK <= T);
    if (full) {
        const int4* sg4 = reinterpret_cast<const int4*>(seg_ids + base);
        const int4* fi4 = reinterpret_cast<const int4*>(flat_items + base);
        #pragma unroll
        for (int v = 0; v < 4; v++) { sg[v] = sg4[v]; fi[v] = fi4[v]; }
    }

#if __CUDA_ARCH__ >= 900
    cudaGridDependencySynchronize();   // wait for K1 (rowsum + zeroing) to finish
#endif
    if (!inb) return;

    int   cur   = -1;
    int   tgt   = -1;
    float acc_s = 0.0f;
    float acc_c = 0.0f;

    if (full) {
        #pragma unroll
        for (int v = 0; v < 4; v++) {
            #pragma unroll
            for (int k = 0; k < 4; k++) {
                int seg = (k == 0) ? sg[v].x : (k == 1) ? sg[v].y : (k == 2) ? sg[v].z : sg[v].w;
                int it  = (k == 0) ? fi[v].x : (k == 1) ? fi[v].y : (k == 2) ? fi[v].z : fi[v].w;
                if (seg != cur) {
                    if (cur >= 0) {
                        atomicAdd(&g_segsum[cur], acc_s);
                        atomicAdd(&g_segcnt[cur], acc_c);
                    }
                    cur = seg; acc_s = 0.0f; acc_c = 0.0f;
                    tgt = item_idx[seg / 5];
                }
                if (it != tgt) {
                    acc_s += g_rowsum[it];
                    acc_c += 1.0f;
                }
            }
        }
    } else {
        int n = (int)((long)T - base);
        for (int t = 0; t < n; t++) {
            int seg = seg_ids[base + t];
            int it  = flat_items[base + t];
            if (seg != cur) {
                if (cur >= 0) {
                    atomicAdd(&g_segsum[cur], acc_s);
                    atomicAdd(&g_segcnt[cur], acc_c);
                }
                cur = seg; acc_s = 0.0f; acc_c = 0.0f;
                tgt = item_idx[seg / 5];
            }
            if (it != tgt) {
                acc_s += g_rowsum[it];
                acc_c += 1.0f;
            }
        }
    }
    if (cur >= 0) {
        atomicAdd(&g_segsum[cur], acc_s);
        atomicAdd(&g_segcnt[cur], acc_c);
    }
}

// ---------------------------------------------------------------------------
// Kernel 3: combine (PDL: preload biases/indices, sync, read accumulators).
// ---------------------------------------------------------------------------
__global__ void __launch_bounds__(256)
k3_combine(const int*   __restrict__ user_idx,
           const int*   __restrict__ item_idx,
           const float* __restrict__ user_bias,
           const float* __restrict__ item_bias,
           const float* __restrict__ global_avg,
           float* __restrict__ out,
           int Bn) {
    int sample = blockIdx.x * blockDim.x + threadIdx.x;

    int u = 0, i = 0;
    float ub = 0.0f, ib = 0.0f, ga = 0.0f;
    if (sample < Bn) {
        u  = user_idx[sample];
        i  = item_idx[sample];
        ub = user_bias[u];
        ib = item_bias[i];
        ga = global_avg[0];
    }

#if __CUDA_ARCH__ >= 900
    cudaGridDependencySynchronize();   // wait for K2 (and transitively K1)
#endif
    if (sample >= Bn) return;

    float uu = 0.0f;
    #pragma unroll
    for (int r = 0; r < 5; r++) {
        float c = g_segcnt[sample * 5 + r];
        float s = g_segsum[sample * 5 + r];
        if (c > 0.0f) uu += s * rsqrtf(fmaxf(c, 1.0f));
    }
    float rui = g_dot[sample] + uu * g_isum[sample] + ub + ib + ga;
    rui = fminf(fmaxf(rui, 1.0f), 5.0f);
    out[sample] = rui;
}

// ---------------------------------------------------------------------------
// Launch (PDL-chained on the default stream)
// ---------------------------------------------------------------------------
static void launch_pdl(void* func, dim3 grid, dim3 block, void** args) {
    cudaLaunchConfig_t cfg = {};
    cfg.gridDim  = grid;
    cfg.blockDim = block;
    cfg.stream   = 0;
    cudaLaunchAttribute attr[1];
    attr[0].id = cudaLaunchAttributeProgrammaticStreamSerialization;
    attr[0].val.programmaticStreamSerializationAllowed = 1;
    cfg.attrs = attr;
    cfg.numAttrs = 1;
    cudaLaunchKernelExC(&cfg, func, args);
}

extern "C" void kernel_launch(void* const* d_in, const int* in_sizes, int n_in,
                              void* d_out, int out_size) {
    const int*   user_idx   = (const int*)  d_in[0];
    const int*   item_idx   = (const int*)  d_in[1];
    const int*   flat_items = (const int*)  d_in[2];
    const int*   seg_ids    = (const int*)  d_in[3];
    const float* user_emb   = (const float*)d_in[4];
    const float* item_emb   = (const float*)d_in[5];
    const float* Mr         = (const float*)d_in[6];
    const float* user_bias  = (const float*)d_in[7];
    const float* item_bias  = (const float*)d_in[8];
    const float* global_avg = (const float*)d_in[9];
    float* out = (float*)d_out;

    int Bn = in_sizes[0];            // 16384
    int T  = in_sizes[2];            // 1,638,400
    int I  = in_sizes[6] / 64;       // 100000

    int warps = (I + 7) / 8;                      // 12500
    int nprod = (warps * 32 + 255) / 256;         // 1563
    int ndot  = (Bn * 8 + 255) / 256;             // 512
    int nseg  = ((T + CHUNK - 1) / CHUNK + 255) / 256;  // 400
    int ncmb  = (Bn + 255) / 256;                 // 64

    // K1: plain launch (first in chain)
    k1_rowsum_dot<<<nprod + ndot, 256>>>(user_idx, item_idx, user_emb, item_emb,
                                         Mr, Bn, I, nprod);

    // K2: PDL off K1
    {
        void* args[] = { (void*)&flat_items, (void*)&seg_ids, (void*)&item_idx, (void*)&T };
        launch_pdl((void*)k2_seg_accum, dim3(nseg), dim3(256), args);
    }
    // K3: PDL off K2
    {
        void* args[] = { (void*)&user_idx, (void*)&item_idx, (void*)&user_bias,
                         (void*)&item_bias, (void*)&global_avg, (void*)&out, (void*)&Bn };
        launch_pdl((void*)k3_combine, dim3(ncmb), dim3(256), args);
    }
}

// round 9
// speedup vs baseline: 1.3266x; 1.1218x over previous
#include <cuda_runtime.h>
#include <cuda_bf16.h>
#include <cstdint>

#define MAX_I   100000
#define MAX_B   16384
#define NUM_SEG (MAX_B * 5)
#define CHUNK   16

__device__ float g_rowsum[MAX_I];
__device__ float g_segsum[NUM_SEG];
__device__ float g_segcnt[NUM_SEG];
__device__ float g_dot[MAX_B];
__device__ float g_isum[MAX_B];

// ---------------------------------------------------------------------------
// Kernel 1: block classes (independent work, no sync):
//   [0, nprod): zero accumulators + rowsum (8 rows/warp, MLP=4)
//   [nprod, ...): per-sample dot/isum precompute (8 lanes/sample)
// ---------------------------------------------------------------------------
__global__ void __launch_bounds__(256)
k1_rowsum_dot(const int*   __restrict__ user_idx,
              const int*   __restrict__ item_idx,
              const float* __restrict__ user_emb,
              const float* __restrict__ item_emb,
              const float* __restrict__ Mr,
              int Bn, int I, int nprod) {
    const int b = blockIdx.x;

    if (b < nprod) {
        const int tid  = b * 256 + threadIdx.x;
        if (tid < NUM_SEG) {
            g_segsum[tid] = 0.0f;
            g_segcnt[tid] = 0.0f;
        }
        const int warp = tid >> 5;
        const int lane = threadIdx.x & 31;
        const int row0 = warp * 8;
        if (row0 >= I) return;

        const float4* base = reinterpret_cast<const float4*>(Mr) + (long)row0 * 16;

        float s[4];
        if (row0 + 8 <= I) {
            #pragma unroll
            for (int j = 0; j < 4; j++) {
                float4 v = base[j * 32 + lane];
                s[j] = (v.x + v.y) + (v.z + v.w);
            }
        } else {
            #pragma unroll
            for (int j = 0; j < 4; j++) {
                int f = j * 32 + lane;
                int r = row0 + (f >> 4);
                if (r < I) {
                    float4 v = base[f];
                    s[j] = (v.x + v.y) + (v.z + v.w);
                } else s[j] = 0.0f;
            }
        }
        #pragma unroll
        for (int o = 8; o; o >>= 1) {
            #pragma unroll
            for (int j = 0; j < 4; j++)
                s[j] += __shfl_xor_sync(0xFFFFFFFFu, s[j], o);
        }
        if ((lane & 15) == 0) {
            int rbase = row0 + (lane >> 4);
            #pragma unroll
            for (int j = 0; j < 4; j++) {
                int r = rbase + j * 2;
                if (r < I) g_rowsum[r] = s[j];
            }
        }
    } else {
        int t2     = (b - nprod) * 256 + threadIdx.x;
        int sample = t2 >> 3;
        int sub    = t2 & 7;
        if (sample >= Bn) return;

        int u = user_idx[sample];
        int i = item_idx[sample];

        const float4* ue = reinterpret_cast<const float4*>(user_emb + (long)u * 64);
        const float4* ie = reinterpret_cast<const float4*>(item_emb + (long)i * 64);

        float4 a0 = ue[sub];
        float4 a1 = ue[sub + 8];
        float4 b0 = ie[sub];
        float4 b1 = ie[sub + 8];

        float dot  = a0.x*b0.x + a0.y*b0.y + a0.z*b0.z + a0.w*b0.w
                   + a1.x*b1.x + a1.y*b1.y + a1.z*b1.z + a1.w*b1.w;
        float isum = b0.x + b0.y + b0.z + b0.w + b1.x + b1.y + b1.z + b1.w;

        #pragma unroll
        for (int o = 4; o; o >>= 1) {
            dot  += __shfl_xor_sync(0xFFFFFFFFu, dot,  o);
            isum += __shfl_xor_sync(0xFFFFFFFFu, isum, o);
        }
        if (sub == 0) {
            g_dot[sample]  = dot;
            g_isum[sample] = isum;
        }
    }
}

// ---------------------------------------------------------------------------
// Kernel 2: segmented accumulation with batched prefetch.
// Per element k, the match test only needs element k's OWN segment's target
// item, so prefetch rs[k]=rowsum[fi[k]] and tg[k]=item_idx[sg[k]/5] for all
// 16 elements unconditionally (parallel loads), then run-length flush on
// registers only.
// ---------------------------------------------------------------------------
__global__ void __launch_bounds__(256)
k2_seg_accum(const int* __restrict__ flat_items,
             const int* __restrict__ seg_ids,
             const int* __restrict__ item_idx,
             int T) {
    long base = (long)(blockIdx.x * blockDim.x + threadIdx.x) * CHUNK;
    if (base >= T) return;

    if (base + CHUNK <= T) {
        const int4* sg4 = reinterpret_cast<const int4*>(seg_ids + base);
        const int4* fi4 = reinterpret_cast<const int4*>(flat_items + base);

        int sgv[16], fiv[16];
        #pragma unroll
        for (int v = 0; v < 4; v++) {
            int4 sg = sg4[v];
            int4 fi = fi4[v];
            sgv[v*4+0] = sg.x; sgv[v*4+1] = sg.y; sgv[v*4+2] = sg.z; sgv[v*4+3] = sg.w;
            fiv[v*4+0] = fi.x; fiv[v*4+1] = fi.y; fiv[v*4+2] = fi.z; fiv[v*4+3] = fi.w;
        }

        // Batched independent gathers (MLP ~32)
        float rs[16];
        int   tg[16];
        #pragma unroll
        for (int k = 0; k < 16; k++) rs[k] = __ldg(&g_rowsum[fiv[k]]);
        #pragma unroll
        for (int k = 0; k < 16; k++) tg[k] = __ldg(&item_idx[sgv[k] / 5]);

        // Run-length flush, registers only
        int   cur   = sgv[0];
        float acc_s = 0.0f;
        float acc_c = 0.0f;
        #pragma unroll
        for (int k = 0; k < 16; k++) {
            if (sgv[k] != cur) {
                atomicAdd(&g_segsum[cur], acc_s);
                atomicAdd(&g_segcnt[cur], acc_c);
                cur = sgv[k]; acc_s = 0.0f; acc_c = 0.0f;
            }
            if (fiv[k] != tg[k]) {
                acc_s += rs[k];
                acc_c += 1.0f;
            }
        }
        atomicAdd(&g_segsum[cur], acc_s);
        atomicAdd(&g_segcnt[cur], acc_c);
    } else {
        int n = (int)((long)T - base);
        int   cur   = -1;
        float acc_s = 0.0f;
        float acc_c = 0.0f;
        for (int t = 0; t < n; t++) {
            int seg = seg_ids[base + t];
            int it  = flat_items[base + t];
            if (seg != cur) {
                if (cur >= 0) {
                    atomicAdd(&g_segsum[cur], acc_s);
                    atomicAdd(&g_segcnt[cur], acc_c);
                }
                cur = seg; acc_s = 0.0f; acc_c = 0.0f;
            }
            if (it != item_idx[seg / 5]) {
                acc_s += g_rowsum[it];
                acc_c += 1.0f;
            }
        }
        if (cur >= 0) {
            atomicAdd(&g_segsum[cur], acc_s);
            atomicAdd(&g_segcnt[cur], acc_c);
        }
    }
}

// ---------------------------------------------------------------------------
// Kernel 3: combine. One thread per sample, branch-free, all loads up front.
// ---------------------------------------------------------------------------
__global__ void __launch_bounds__(256)
k3_combine(const int*   __restrict__ user_idx,
           const int*   __restrict__ item_idx,
           const float* __restrict__ user_bias,
           const float* __restrict__ item_bias,
           const float* __restrict__ global_avg,
           float* __restrict__ out,
           int Bn) {
    int sample = blockIdx.x * blockDim.x + threadIdx.x;
    if (sample >= Bn) return;

    int u = user_idx[sample];
    int i = item_idx[sample];

    float c[5], s[5];
    #pragma unroll
    for (int r = 0; r < 5; r++) {
        c[r] = __ldg(&g_segcnt[sample * 5 + r]);
        s[r] = __ldg(&g_segsum[sample * 5 + r]);
    }
    float dt = __ldg(&g_dot[sample]);
    float is = __ldg(&g_isum[sample]);
    float ub = __ldg(&user_bias[u]);
    float ib = __ldg(&item_bias[i]);
    float ga = __ldg(&global_avg[0]);

    float uu = 0.0f;
    #pragma unroll
    for (int r = 0; r < 5; r++) {
        float m = (c[r] > 0.0f) ? 1.0f : 0.0f;
        uu += m * s[r] * rsqrtf(fmaxf(c[r], 1.0f));
    }
    float rui = dt + uu * is + ub + ib + ga;
    rui = fminf(fmaxf(rui, 1.0f), 5.0f);
    out[sample] = rui;
}

// ---------------------------------------------------------------------------
// Launch (plain stream-ordered — overlap mechanisms all regressed)
// ---------------------------------------------------------------------------
extern "C" void kernel_launch(void* const* d_in, const int* in_sizes, int n_in,
                              void* d_out, int out_size) {
    const int*   user_idx   = (const int*)  d_in[0];
    const int*   item_idx   = (const int*)  d_in[1];
    const int*   flat_items = (const int*)  d_in[2];
    const int*   seg_ids    = (const int*)  d_in[3];
    const float* user_emb   = (const float*)d_in[4];
    const float* item_emb   = (const float*)d_in[5];
    const float* Mr         = (const float*)d_in[6];
    const float* user_bias  = (const float*)d_in[7];
    const float* item_bias  = (const float*)d_in[8];
    const float* global_avg = (const float*)d_in[9];
    float* out = (float*)d_out;

    int Bn = in_sizes[0];            // 16384
    int T  = in_sizes[2];            // 1,638,400
    int I  = in_sizes[6] / 64;       // 100000

    int warps = (I + 7) / 8;                            // 12500
    int nprod = (warps * 32 + 255) / 256;               // 1563
    int ndot  = (Bn * 8 + 255) / 256;                   // 512
    int nseg  = ((T + CHUNK - 1) / CHUNK + 255) / 256;  // 400
    int ncmb  = (Bn + 255) / 256;                       // 64

    k1_rowsum_dot<<<nprod + ndot, 256>>>(user_idx, item_idx, user_emb, item_emb,
                                         Mr, Bn, I, nprod);
    k2_seg_accum<<<nseg, 256>>>(flat_items, seg_ids, item_idx, T);
    k3_combine<<<ncmb, 256>>>(user_idx, item_idx, user_bias, item_bias,
                              global_avg, out, Bn);
}